// round 8
// baseline (speedup 1.0000x reference)
#include <cuda_runtime.h>

#define TCOLS 4096
#define BROWS 4096
#define NT 512
#define FULL 0xffffffffu

// g_res rows: 0 pred_sbp, 1 pred_dbp, 2 lab_sbp, 3 lab_dbp
__device__ float    g_res[4][BROWS];
__device__ unsigned g_done;   // zero-init; reset by last block each launch

__device__ __forceinline__ float warp_sum(float v) {
    #pragma unroll
    for (int o = 16; o; o >>= 1) v += __shfl_xor_sync(FULL, v, o);
    return v;
}

// Per-group (8 warps) reduction of 2 sums + 2 counts; broadcast into out[4].
// redf: [grp*32 + j*8 + w8] partials, [64 + grp*4 + j] results (72 floats).
__device__ __forceinline__ void group_reduce4(float s0, float s1, int c0, int c1,
                                              float out[4], float* redf,
                                              int lane, int w8, int grp) {
    s0 = warp_sum(s0);
    s1 = warp_sum(s1);
    c0 = __reduce_add_sync(FULL, c0);
    c1 = __reduce_add_sync(FULL, c1);
    if (lane == 0) {
        redf[grp * 32 + 0 * 8 + w8] = s0;
        redf[grp * 32 + 1 * 8 + w8] = s1;
        redf[grp * 32 + 2 * 8 + w8] = (float)c0;
        redf[grp * 32 + 3 * 8 + w8] = (float)c1;
    }
    __syncthreads();
    if (w8 < 4) {   // warps 0-3 reduce grp0's 4 values, warps 8-11 grp1's
        float v = (lane < 8) ? redf[grp * 32 + w8 * 8 + lane] : 0.f;
        v += __shfl_xor_sync(FULL, v, 4);
        v += __shfl_xor_sync(FULL, v, 2);
        v += __shfl_xor_sync(FULL, v, 1);
        if (lane == 0) redf[64 + grp * 4 + w8] = v;
    }
    __syncthreads();
    #pragma unroll
    for (int j = 0; j < 4; j++) out[j] = redf[64 + grp * 4 + j];
    __syncthreads();   // redf free for next reduction
}

__global__ __launch_bounds__(NT, 3)
void pv_fused_kernel(const float* __restrict__ preds,
                     const float* __restrict__ labels,
                     float* __restrict__ out) {
    __shared__ float red[72];
    __shared__ bool  amLast;

    const int tid  = threadIdx.x;
    const int lane = tid & 31;
    const int wid  = tid >> 5;
    const int grp  = wid >> 3;        // 0 = preds, 1 = labels
    const int w8   = wid & 7;
    const int row  = blockIdx.x;
    const int wb   = w8 * 512;

    const float* rowp = (grp ? labels : preds) + ((size_t)row << 12);
    const float4* g   = (const float4*)(rowp + wb);

    // Clamped duplicate neighbors at row edges -> d == 0 -> never strict peak/valley.
    float wl = 0.f, wr = 0.f;
    if (lane == 0)  wl = rowp[wb ? wb - 1 : 0];
    if (lane == 31) wr = rowp[wb + 512 < TCOLS ? wb + 512 : TCOLS - 1];

    // ---- Load lane's 16 elements (coalesced float4 groups) ----
    float v[16];
    #pragma unroll
    for (int gi = 0; gi < 4; gi++) {
        float4 a = g[gi * 32 + lane];
        v[4 * gi] = a.x; v[4 * gi + 1] = a.y; v[4 * gi + 2] = a.z; v[4 * gi + 3] = a.w;
    }

    // ---- Pass 1: peak/valley detect (shuffle-stitched windows) ----
    float psum = 0.f, vsum = 0.f;
    unsigned pkm = 0, vym = 0;
    float carry = wl;
    #pragma unroll
    for (int gi = 0; gi < 4; gi++) {
        float lead = (gi < 3) ? __shfl_sync(FULL, v[4 * gi + 4], 0) : wr;
        float lv = __shfl_up_sync(FULL, v[4 * gi + 3], 1);
        if (lane == 0) lv = carry;
        float rv = __shfl_down_sync(FULL, v[4 * gi], 1);
        if (lane == 31) rv = lead;
        carry = __shfl_sync(FULL, v[4 * gi + 3], 31);

        float e0 = v[4 * gi], e1 = v[4 * gi + 1], e2 = v[4 * gi + 2], e3 = v[4 * gi + 3];
        float d[5];
        d[0] = e0 - lv; d[1] = e1 - e0; d[2] = e2 - e1; d[3] = e3 - e2; d[4] = rv - e3;
        float e[4] = {e0, e1, e2, e3};
        #pragma unroll
        for (int k = 0; k < 4; k++) {
            if (fminf(d[k], -d[k + 1]) > 0.f) { psum += e[k]; pkm |= 1u << (4 * gi + k); }
            if (fmaxf(d[k], -d[k + 1]) < 0.f) { vsum += e[k]; vym |= 1u << (4 * gi + k); }
        }
    }

    float o1[4];
    group_reduce4(psum, vsum, __popc(pkm), __popc(vym), o1, red, lane, w8, grp);
    const float pm = o1[0] / o1[2];
    const float vm = o1[1] / o1[3];

    // ---- Pass 2: thresholded masked means from registers ----
    float s0 = 0.f, s1 = 0.f;
    int   c0 = 0,   c1 = 0;
    #pragma unroll
    for (int k = 0; k < 16; k++) {
        const unsigned bit = 1u << k;
        if ((pkm & bit) && v[k] >= pm) { s0 += v[k]; c0++; }
        if ((vym & bit) && v[k] <= vm) { s1 += v[k]; c1++; }
    }

    float o2[4];
    group_reduce4(s0, s1, c0, c1, o2, red, lane, w8, grp);

    if (lane == 0 && w8 == 0) {               // tid 0 (preds) and tid 256 (labels)
        g_res[(grp << 1) + 0][row] = o2[0] / o2[2];
        g_res[(grp << 1) + 1][row] = o2[1] / o2[3];
    }
    __syncthreads();
    if (tid == 0) {
        __threadfence();
        unsigned c = atomicAdd(&g_done, 1u);
        amLast = (c == (unsigned)(gridDim.x - 1));
    }
    __syncthreads();

    // ---- Last block: combine per-row results into the scalar loss ----
    if (amLast) {
        float acc = 0.f;
        #pragma unroll
        for (int q = 0; q < BROWS / NT; q++) {
            int r = tid + q * NT;
            float d0 = g_res[0][r] - g_res[2][r];
            float d1 = g_res[1][r] - g_res[3][r];
            acc += d0 * d0 + d1 * d1;
        }
        acc = warp_sum(acc);
        if (lane == 0) red[wid] = acc;
        __syncthreads();
        if (tid == 0) {
            float t = 0.f;
            #pragma unroll
            for (int w = 0; w < NT / 32; w++) t += red[w];
            out[0] = t / (float)(BROWS * 2);
            g_done = 0;
        }
    }
}

extern "C" void kernel_launch(void* const* d_in, const int* in_sizes, int n_in,
                              void* d_out, int out_size) {
    const float* preds  = (const float*)d_in[0];
    const float* labels = (const float*)d_in[1];
    pv_fused_kernel<<<BROWS, NT>>>(preds, labels, (float*)d_out);
}